// round 15
// baseline (speedup 1.0000x reference)
#include <cuda_runtime.h>
#include <cuda_fp16.h>
#include <cstdint>
#include <math.h>

#define BB 65536
#define FDIM 267
#define HDIM 256
#define LDIM 64
#define KCODE 1024

#define KU1 288   // fc1: K=534 padded 576
#define KU2 128   // K=256
#define KU4 192   // fc4: K=331 padded 384

// ---------------- device globals ----------------
__device__ float g_esq[KCODE];
__device__ int   g_counts[KCODE];
__device__ float g_partials[512];
__device__ uint32_t g_eth[KCODE * 32], g_etl[KCODE * 32];
__device__ uint2 g_w1i[256 * KU1];
__device__ uint2 g_w2i[256 * KU2];
__device__ uint2 g_w3i[256 * KU2];
__device__ uint2 g_wmi[128 * KU2];
__device__ uint2 g_w4i[256 * KU4];
__device__ uint2 g_w5i[256 * KU2];
__device__ uint2 g_w6i[256 * KU2];
__device__ uint2 g_woi[384 * KU2];

// ---------------- helpers ----------------
__device__ __forceinline__ float hi32(float a) {
    return __uint_as_float(__float_as_uint(a) & 0xFFFFE000u);
}
__device__ __forceinline__ uint32_t packh(float x, float y) {
    uint32_t d;
    asm("cvt.rn.f16x2.f32 %0, %1, %2;" : "=r"(d) : "f"(y), "f"(x));
    return d;
}
__device__ __forceinline__ uint32_t split_pack(float a, float b, uint32_t& lo) {
    float ha = hi32(a), hb = hi32(b);
    lo = packh(a - ha, b - hb);
    return packh(ha, hb);
}
__device__ __forceinline__ uint32_t smem_u32(const void* p) {
    uint32_t a;
    asm("{ .reg .u64 t; cvta.to.shared.u64 t, %1; cvt.u32.u64 %0, t; }" : "=r"(a) : "l"(p));
    return a;
}
__device__ __forceinline__ void ldm_x4(uint32_t* d, uint32_t a) {
    asm volatile("ldmatrix.sync.aligned.m8n8.x4.shared.b16 {%0,%1,%2,%3}, [%4];"
        : "=r"(d[0]), "=r"(d[1]), "=r"(d[2]), "=r"(d[3]) : "r"(a));
}
__device__ __forceinline__ void mma16(float* d, const uint32_t* a, const uint32_t* b) {
    asm volatile(
        "mma.sync.aligned.m16n8k16.row.col.f32.f16.f16.f32 "
        "{%0,%1,%2,%3},{%4,%5,%6,%7},{%8,%9},{%0,%1,%2,%3};"
        : "+f"(d[0]), "+f"(d[1]), "+f"(d[2]), "+f"(d[3])
        : "r"(a[0]), "r"(a[1]), "r"(a[2]), "r"(a[3]), "r"(b[0]), "r"(b[1]));
}

// smem u32 map (dynamic, 55296 u32 = 221184 B):
//   ACT  [0, 36864)      : activation pairs, 4 chunks x (hi 4608 | lo 4608)
//                          also: streamed-A staging (2 bufs x 9216 at [0,18432))
//                          VQ: E tiles [0,9216), esq [9216,10240), q pairs [27648,36864)
//   BBUF [36864, 55296)  : B double buffer (2 x 9216) ; VQ: Mh/Ml at [46080, 55296)
#define U_ACT  0
#define U_BB   36864
#define U_MH   46080
#define U_ML   50688
#define U_QH   27648
#define U_QL   32256
#define U_ESQ  9216

__global__ void __launch_bounds__(512, 1) fused_net(
    const float* __restrict__ x, const float* __restrict__ cc,
    const float* __restrict__ fc1_b, const float* __restrict__ fc2_b,
    const float* __restrict__ fc3_b, const float* __restrict__ mu_b,
    const float* __restrict__ fc4_b, const float* __restrict__ fc5_b,
    const float* __restrict__ fc6_b, const float* __restrict__ out_b,
    const float* __restrict__ embed, float* __restrict__ outp)
{
    extern __shared__ uint32_t smv[];
    __shared__ float sbest[16][2][2][8];
    __shared__ int   sidx[16][2][2][8];
    __shared__ int   rowidx[128];
    __shared__ float wsum[16];

    const int tid = threadIdx.x, lane = tid & 31, wid = tid >> 5;
    const int m0 = blockIdx.x * 128;
    const int wm0 = (wid >> 2) * 32, wq = wid & 3, wn0 = wq * 32;
    const int r = lane >> 2, kq = lane & 3;
    const int prow = tid >> 4, pj = tid & 15;
    const int g = lane >> 3, lr = lane & 7;
    const uint32_t sb = smem_u32(smv);

    // fragment lane addresses (byte)
    uint32_t aF[2], bF[2], bFmu;
    #pragma unroll
    for (int mt = 0; mt < 2; mt++) {
        const uint32_t row = wm0 + mt * 16 + (g & 1) * 8 + lr;
        aF[mt] = sb + 4u * (row * 36 + (g >> 1) * 4);
    }
    #pragma unroll
    for (int np = 0; np < 2; np++) {
        const uint32_t n = wn0 + (2 * np + (g >> 1)) * 8 + lr;
        bF[np] = sb + 4u * (U_BB + n * 36 + (g & 1) * 4);
    }
    { const uint32_t n = wq * 16 + (g >> 1) * 8 + lr;
      bFmu = sb + 4u * (U_BB + n * 36 + (g & 1) * 4); }

    float acc[2][4][4];
    uint4 bU[4];
    float4 a4[4];
    uint2 rp[2][16];

    auto zacc = [&] {
        #pragma unroll
        for (int i = 0; i < 2; i++)
            #pragma unroll
            for (int j = 0; j < 4; j++)
                #pragma unroll
                for (int e = 0; e < 4; e++) acc[i][j][e] = 0.f;
    };
    auto pfB = [&](const uint2* Wt, int KUb, int rowoff, int c) {
        const size_t bo = (size_t)c * 32 + 2 * pj;
        #pragma unroll
        for (int p = 0; p < 4; p++)
            bU[p] = *(const uint4*)&Wt[(size_t)(rowoff + p * 32 + prow) * KUb + bo];
    };
    auto stB = [&](int b) {
        uint32_t* base = smv + U_BB + b * 9216;
        #pragma unroll
        for (int p = 0; p < 4; p++) {
            const int o = (p * 32 + prow) * 36 + 2 * pj;
            base[o] = bU[p].x; base[o + 1] = bU[p].z;
            base[4608 + o] = bU[p].y; base[4608 + o + 1] = bU[p].w;
        }
    };
    auto stA = [&](int b) {   // split a4 -> staging buf b
        uint32_t* base = smv + b * 9216;
        #pragma unroll
        for (int p = 0; p < 4; p++) {
            const int o = (p * 32 + prow) * 36 + 2 * pj;
            const float h0 = hi32(a4[p].x), h1 = hi32(a4[p].y);
            const float h2 = hi32(a4[p].z), h3 = hi32(a4[p].w);
            base[o]            = packh(h0, h1);
            base[o + 1]        = packh(h2, h3);
            base[4608 + o]     = packh(a4[p].x - h0, a4[p].y - h1);
            base[4608 + o + 1] = packh(a4[p].z - h2, a4[p].w - h3);
        }
    };
    auto computeChunk = [&](uint32_t aOff, uint32_t bOff) {
        #pragma unroll
        for (int ks = 0; ks < 4; ks++) {
            const uint32_t ko = ks * 32u;
            uint32_t ah[2][4], al[2][4], bh[4][2], bl[4][2];
            ldm_x4(ah[0], aF[0] + aOff + ko);
            ldm_x4(ah[1], aF[1] + aOff + ko);
            ldm_x4(al[0], aF[0] + aOff + ko + 18432u);
            ldm_x4(al[1], aF[1] + aOff + ko + 18432u);
            ldm_x4(&bh[0][0], bF[0] + bOff + ko);
            ldm_x4(&bh[2][0], bF[1] + bOff + ko);
            ldm_x4(&bl[0][0], bF[0] + bOff + ko + 18432u);
            ldm_x4(&bl[2][0], bF[1] + bOff + ko + 18432u);
            #pragma unroll
            for (int mt = 0; mt < 2; mt++)
                #pragma unroll
                for (int nt = 0; nt < 4; nt++) {
                    mma16(acc[mt][nt], ah[mt], bh[nt]);
                    mma16(acc[mt][nt], ah[mt], bl[nt]);
                    mma16(acc[mt][nt], al[mt], bh[nt]);
                }
        }
    };
    auto passResident = [&](const uint2* Wt, int rowoff) {
        zacc();
        pfB(Wt, KU2, rowoff, 0); stB(0); __syncthreads();
        #pragma unroll
        for (int c = 0; c < 4; c++) {
            if (c < 3) pfB(Wt, KU2, rowoff, c + 1);
            computeChunk((uint32_t)c * 36864u, (uint32_t)(c & 1) * 36864u);
            if (c < 3) stB((c + 1) & 1);
            __syncthreads();
        }
    };
    auto accPack = [&](const float* bias, int nbase, uint2* dst) {
        int i = 0;
        #pragma unroll
        for (int mt = 0; mt < 2; mt++)
            #pragma unroll
            for (int q = 0; q < 2; q++)
                #pragma unroll
                for (int nt = 0; nt < 4; nt++) {
                    const int n = nbase + wn0 + nt * 8 + 2 * kq;
                    float o0 = fmaxf(acc[mt][nt][q * 2 + 0] + bias[n], 0.f);
                    float o1 = fmaxf(acc[mt][nt][q * 2 + 1] + bias[n + 1], 0.f);
                    uint32_t l; uint32_t h = split_pack(o0, o1, l);
                    dst[i++] = make_uint2(h, l);
                }
    };
    auto writeACT = [&] {
        #pragma unroll
        for (int nb = 0; nb < 2; nb++) {
            int i = 0;
            #pragma unroll
            for (int mt = 0; mt < 2; mt++)
                #pragma unroll
                for (int q = 0; q < 2; q++)
                    #pragma unroll
                    for (int nt = 0; nt < 4; nt++) {
                        const int row = wm0 + mt * 16 + q * 8 + r;
                        const int n = nb * 128 + wn0 + nt * 8 + 2 * kq;
                        const int idx = (n >> 6) * 9216 + row * 36 + ((n >> 1) & 31);
                        smv[idx] = rp[nb][i].x;
                        smv[idx + 4608] = rp[nb][i].y;
                        i++;
                    }
        }
    };
    auto layer256 = [&](const uint2* Wt, const float* bias) {
        passResident(Wt, 0);   accPack(bias, 0, rp[0]);
        passResident(Wt, 128); accPack(bias, 128, rp[1]);
        writeACT();
    };

    // ===== fc1: streamed A = x||c, K=576 (9 chunks) =====
    {
        auto pfA1 = [&](int c) {
            const int kg0 = c * 64 + 4 * pj;
            #pragma unroll
            for (int p = 0; p < 4; p++) {
                const int rowg = m0 + p * 32 + prow;
                float v[4];
                #pragma unroll
                for (int e = 0; e < 4; e++) {
                    const int kg = kg0 + e;
                    v[e] = (kg < FDIM) ? x[(size_t)rowg * FDIM + kg]
                         : (kg < 534 ? cc[(size_t)rowg * FDIM + kg - FDIM] : 0.f);
                }
                a4[p] = make_float4(v[0], v[1], v[2], v[3]);
            }
        };
        #pragma unroll 1
        for (int nb = 0; nb < 2; nb++) {
            zacc();
            pfA1(0); pfB(g_w1i, KU1, nb * 128, 0);
            stA(0); stB(0); __syncthreads();
            #pragma unroll 1
            for (int c = 0; c < 9; c++) {
                if (c < 8) { pfA1(c + 1); pfB(g_w1i, KU1, nb * 128, c + 1); }
                computeChunk((uint32_t)(c & 1) * 36864u, (uint32_t)(c & 1) * 36864u);
                if (c < 8) { stA((c + 1) & 1); stB((c + 1) & 1); }
                __syncthreads();
            }
            accPack(fc1_b, nb * 128, rp[nb]);
        }
        writeACT();
    }

    // ===== fc2, fc3 =====
    layer256(g_w2i, fc2_b);
    layer256(g_w3i, fc3_b);

    // ===== mu: resident A, N=64 -> Mh/Ml =====
    {
        float accm[2][2][4];
        #pragma unroll
        for (int i = 0; i < 2; i++)
            #pragma unroll
            for (int j = 0; j < 2; j++)
                #pragma unroll
                for (int e = 0; e < 4; e++) accm[i][j][e] = 0.f;
        uint4 bU2[2];
        auto pfBmu = [&](int c) {
            const size_t bo = (size_t)c * 32 + 2 * pj;
            #pragma unroll
            for (int p = 0; p < 2; p++)
                bU2[p] = *(const uint4*)&g_wmi[(size_t)(p * 32 + prow) * KU2 + bo];
        };
        auto stBmu = [&](int b) {
            uint32_t* base = smv + U_BB + b * 4608;
            #pragma unroll
            for (int p = 0; p < 2; p++) {
                const int o = (p * 32 + prow) * 36 + 2 * pj;
                base[o] = bU2[p].x; base[o + 1] = bU2[p].z;
                base[2304 + o] = bU2[p].y; base[2304 + o + 1] = bU2[p].w;
            }
        };
        pfBmu(0); stBmu(0); __syncthreads();
        #pragma unroll
        for (int c = 0; c < 4; c++) {
            if (c < 3) pfBmu(c + 1);
            const uint32_t aOff = (uint32_t)c * 36864u;
            const uint32_t bOff = (uint32_t)(c & 1) * 18432u;
            #pragma unroll
            for (int ks = 0; ks < 4; ks++) {
                const uint32_t ko = ks * 32u;
                uint32_t ah[2][4], al[2][4], b2h[4], b2l[4];
                ldm_x4(ah[0], aF[0] + aOff + ko);
                ldm_x4(ah[1], aF[1] + aOff + ko);
                ldm_x4(al[0], aF[0] + aOff + ko + 18432u);
                ldm_x4(al[1], aF[1] + aOff + ko + 18432u);
                ldm_x4(b2h, bFmu + bOff + ko);
                ldm_x4(b2l, bFmu + bOff + ko + 9216u);
                #pragma unroll
                for (int mt = 0; mt < 2; mt++)
                    #pragma unroll
                    for (int nt = 0; nt < 2; nt++) {
                        mma16(accm[mt][nt], ah[mt], &b2h[nt * 2]);
                        mma16(accm[mt][nt], ah[mt], &b2l[nt * 2]);
                        mma16(accm[mt][nt], al[mt], &b2h[nt * 2]);
                    }
            }
            if (c < 3) stBmu((c + 1) & 1);
            __syncthreads();
        }
        // epilogue -> Mh/Ml (disjoint from mu B staging)
        #pragma unroll
        for (int mt = 0; mt < 2; mt++)
            #pragma unroll
            for (int q = 0; q < 2; q++) {
                const int m = wm0 + mt * 16 + q * 8 + r;
                #pragma unroll
                for (int nt = 0; nt < 2; nt++) {
                    const int n = wq * 16 + nt * 8 + 2 * kq;
                    const float o0 = accm[mt][nt][q * 2 + 0] + mu_b[n];
                    const float o1 = accm[mt][nt][q * 2 + 1] + mu_b[n + 1];
                    uint32_t l; uint32_t h = split_pack(o0, o1, l);
                    smv[U_MH + m * 36 + (n >> 1)] = h;
                    smv[U_ML + m * 36 + (n >> 1)] = l;
                }
            }
    }

    // ===== VQ argmin (R13 logic; M at U_MH, E at ACT[0..9216)) =====
    {
        float* esq_s = (float*)(smv + U_ESQ);
        #pragma unroll
        for (int i = tid; i < KCODE; i += 512) esq_s[i] = g_esq[i];

        float best[2][2];
        int   bidx[2][2];
        #pragma unroll
        for (int i = 0; i < 2; i++)
            #pragma unroll
            for (int j = 0; j < 2; j++) { best[i][j] = 3.4e38f; bidx[i][j] = 0; }

        uint32_t aM[2], aE[2];
        #pragma unroll
        for (int mt = 0; mt < 2; mt++) {
            const uint32_t row = wm0 + mt * 16 + (g & 1) * 8 + lr;
            aM[mt] = sb + 4u * (U_MH + row * 36 + (g >> 1) * 4);
        }
        #pragma unroll
        for (int np = 0; np < 2; np++) {
            const uint32_t n = wn0 + (2 * np + (g >> 1)) * 8 + lr;
            aE[np] = sb + 4u * (n * 36 + (g & 1) * 4);
        }

        uint32_t uh[8], ul[8];
        #pragma unroll 1
        for (int ct = 0; ct < 8; ct++) {
            #pragma unroll
            for (int ps = 0; ps < 8; ps++) {
                const int row = ps * 16 + wid;
                uh[ps] = g_eth[(size_t)(ct * 128 + row) * 32 + lane];
                ul[ps] = g_etl[(size_t)(ct * 128 + row) * 32 + lane];
            }
            __syncthreads();
            #pragma unroll
            for (int ps = 0; ps < 8; ps++) {
                const int row = ps * 16 + wid;
                smv[row * 36 + lane] = uh[ps];
                smv[4608 + row * 36 + lane] = ul[ps];
            }
            __syncthreads();

            zacc();
            #pragma unroll
            for (int ks = 0; ks < 4; ks++) {
                const uint32_t ko = ks * 32u;
                uint32_t ah[2][4], al[2][4], bh[4][2], bl[4][2];
                ldm_x4(ah[0], aM[0] + ko);
                ldm_x4(ah[1], aM[1] + ko);
                ldm_x4(al[0], aM[0] + ko + 18432u);
                ldm_x4(al[1], aM[1] + ko + 18432u);
                ldm_x4(&bh[0][0], aE[0] + ko);
                ldm_x4(&bh[2][0], aE[1] + ko);
                ldm_x4(&bl[0][0], aE[0] + ko + 18432u);
                ldm_x4(&bl[2][0], aE[1] + ko + 18432u);
                #pragma unroll
                for (int mt = 0; mt < 2; mt++)
                    #pragma unroll
                    for (int nt = 0; nt < 4; nt++) {
                        mma16(acc[mt][nt], ah[mt], bh[nt]);
                        mma16(acc[mt][nt], ah[mt], bl[nt]);
                        mma16(acc[mt][nt], al[mt], bh[nt]);
                    }
            }
            #pragma unroll
            for (int mt = 0; mt < 2; mt++)
                #pragma unroll
                for (int q = 0; q < 2; q++)
                    #pragma unroll
                    for (int nt = 0; nt < 4; nt++)
                        #pragma unroll
                        for (int e = 0; e < 2; e++) {
                            const int code = ct * 128 + wn0 + nt * 8 + 2 * kq + e;
                            const float sc = esq_s[code] - 2.f * acc[mt][nt][q * 2 + e];
                            if (sc < best[mt][q]) { best[mt][q] = sc; bidx[mt][q] = code; }
                        }
            __syncthreads();
        }

        #pragma unroll
        for (int mt = 0; mt < 2; mt++)
            #pragma unroll
            for (int q = 0; q < 2; q++) {
                float b = best[mt][q]; int ix = bidx[mt][q];
                #pragma unroll
                for (int s = 1; s <= 2; s <<= 1) {
                    const float ob = __shfl_xor_sync(0xffffffffu, b, s);
                    const int   oi = __shfl_xor_sync(0xffffffffu, ix, s);
                    if (ob < b || (ob == b && oi < ix)) { b = ob; ix = oi; }
                }
                if (kq == 0) { sbest[wid][mt][q][r] = b; sidx[wid][mt][q][r] = ix; }
            }
        __syncthreads();
        if (wq == 0 && kq == 0) {
            #pragma unroll
            for (int mt = 0; mt < 2; mt++)
                #pragma unroll
                for (int q = 0; q < 2; q++) {
                    float b0 = sbest[wid][mt][q][r]; int i0 = sidx[wid][mt][q][r];
                    #pragma unroll
                    for (int w2 = 1; w2 < 4; w2++) {
                        float b1 = sbest[wid + w2][mt][q][r]; int i1 = sidx[wid + w2][mt][q][r];
                        if (b1 < b0 || (b1 == b0 && i1 < i0)) { b0 = b1; i0 = i1; }
                    }
                    rowidx[wm0 + mt * 16 + r + q * 8] = i0;
                }
        }
        __syncthreads();

        // gather q (pairs -> U_QH/U_QL) + loss + histogram
        float lsum = 0.f;
        #pragma unroll
        for (int rr = 0; rr < 8; rr++) {
            const int row = wid * 8 + rr;
            const int idx = rowidx[row];
            const float e0 = embed[(size_t)(2 * lane) * KCODE + idx];
            const float e1 = embed[(size_t)(2 * lane + 1) * KCODE + idx];
            uint32_t l; uint32_t h = split_pack(e0, e1, l);
            smv[U_QH + row * 36 + lane] = h;
            smv[U_QL + row * 36 + lane] = l;
            const __half2 H = *(const __half2*)&smv[U_MH + row * 36 + lane];
            const __half2 L = *(const __half2*)&smv[U_ML + row * 36 + lane];
            const float mu0 = __half2float(H.x) + __half2float(L.x);
            const float mu1 = __half2float(H.y) + __half2float(L.y);
            const float d0 = e0 - mu0, d1 = e1 - mu1;
            lsum += d0 * d0 + d1 * d1;
            if (lane == 0) atomicAdd(&g_counts[idx], 1);
        }
        #pragma unroll
        for (int off = 16; off; off >>= 1) lsum += __shfl_down_sync(0xffffffffu, lsum, off);
        if (lane == 0) wsum[wid] = lsum;
        __syncthreads();
        if (tid == 0) {
            float t = 0.f;
            #pragma unroll
            for (int i = 0; i < 16; i++) t += wsum[i];
            g_partials[blockIdx.x] = t;
        }
        __syncthreads();
    }

    // ===== fc4: A = q (smem) || c (global), K=384 (6 chunks) =====
    {
        auto pfA4 = [&](int c) {   // c >= 1 only
            const int kg0 = c * 64 + 4 * pj;
            #pragma unroll
            for (int p = 0; p < 4; p++) {
                const int rowg = m0 + p * 32 + prow;
                float v[4];
                #pragma unroll
                for (int e = 0; e < 4; e++) {
                    const int kg = kg0 + e;
                    v[e] = (kg < 331) ? cc[(size_t)rowg * FDIM + kg - 64] : 0.f;
                }
                a4[p] = make_float4(v[0], v[1], v[2], v[3]);
            }
        };
        #pragma unroll 1
        for (int nb = 0; nb < 2; nb++) {
            zacc();
            // stage chunk 0 = q pairs (copy smem->smem)
            #pragma unroll
            for (int p = 0; p < 4; p++) {
                const int o = (p * 32 + prow) * 36 + 2 * pj;
                smv[o]          = smv[U_QH + o];
                smv[o + 1]      = smv[U_QH + o + 1];
                smv[4608 + o]   = smv[U_QL + o];
                smv[4608 + o + 1] = smv[U_QL + o + 1];
            }
            pfB(g_w4i, KU4, nb * 128, 0); stB(0); __syncthreads();
            #pragma unroll 1
            for (int c = 0; c < 6; c++) {
                if (c < 5) { pfA4(c + 1); pfB(g_w4i, KU4, nb * 128, c + 1); }
                computeChunk((uint32_t)(c & 1) * 36864u, (uint32_t)(c & 1) * 36864u);
                if (c < 5) { stA((c + 1) & 1); stB((c + 1) & 1); }
                __syncthreads();
            }
            accPack(fc4_b, nb * 128, rp[nb]);
        }
        writeACT();
    }

    // ===== fc5, fc6 =====
    layer256(g_w5i, fc5_b);
    layer256(g_w6i, fc6_b);

    // ===== out: N=267 (3 passes, direct global epilogue) =====
    #pragma unroll 1
    for (int nb = 0; nb < 3; nb++) {
        passResident(g_woi, nb * 128);
        #pragma unroll
        for (int mt = 0; mt < 2; mt++)
            #pragma unroll
            for (int q = 0; q < 2; q++) {
                const int rowg = m0 + wm0 + mt * 16 + q * 8 + r;
                #pragma unroll
                for (int nt = 0; nt < 4; nt++) {
                    const int n = nb * 128 + wn0 + nt * 8 + 2 * kq;
                    if (n < FDIM)
                        outp[(size_t)rowg * FDIM + n] = acc[mt][nt][q * 2 + 0] + out_b[n];
                    if (n + 1 < FDIM)
                        outp[(size_t)rowg * FDIM + n + 1] = acc[mt][nt][q * 2 + 1] + out_b[n + 1];
                }
            }
    }
}

// ---------------- fused prep kernel (proven R14) ----------------
__device__ __forceinline__ void wsplit_elem(const float* __restrict__ W, uint2* __restrict__ out,
                                            int N, int K, int KU, int i)
{
    int n = i / KU, j = i - n * KU;
    int k0 = 2 * j;
    float a = (n < N && k0 < K) ? W[(size_t)n * K + k0] : 0.f;
    float b = (n < N && k0 + 1 < K) ? W[(size_t)n * K + k0 + 1] : 0.f;
    uint32_t l; uint32_t h = split_pack(a, b, l);
    out[i] = make_uint2(h, l);
}

#define PB_W1 0
#define PB_W2 (PB_W1 + (256 * KU1) / 256)
#define PB_W3 (PB_W2 + (256 * KU2) / 256)
#define PB_WM (PB_W3 + (256 * KU2) / 256)
#define PB_W4 (PB_WM + (128 * KU2) / 256)
#define PB_W5 (PB_W4 + (256 * KU4) / 256)
#define PB_W6 (PB_W5 + (256 * KU2) / 256)
#define PB_WO (PB_W6 + (256 * KU2) / 256)
#define PB_ET (PB_WO + (384 * KU2) / 256)
#define PB_ZC (PB_ET + (KCODE * 32) / 256)
#define PB_END (PB_ZC + 4)

__global__ void __launch_bounds__(256) prep_all(
    const float* __restrict__ fc1_w, const float* __restrict__ fc2_w,
    const float* __restrict__ fc3_w, const float* __restrict__ mu_w,
    const float* __restrict__ fc4_w, const float* __restrict__ fc5_w,
    const float* __restrict__ fc6_w, const float* __restrict__ out_w,
    const float* __restrict__ embed)
{
    const int b = blockIdx.x, tid = threadIdx.x;
    if (b < PB_W2)      wsplit_elem(fc1_w, g_w1i, 256, 534, KU1, (b - PB_W1) * 256 + tid);
    else if (b < PB_W3) wsplit_elem(fc2_w, g_w2i, 256, 256, KU2, (b - PB_W2) * 256 + tid);
    else if (b < PB_WM) wsplit_elem(fc3_w, g_w3i, 256, 256, KU2, (b - PB_W3) * 256 + tid);
    else if (b < PB_W4) wsplit_elem(mu_w,  g_wmi, 64,  256, KU2, (b - PB_WM) * 256 + tid);
    else if (b < PB_W5) wsplit_elem(fc4_w, g_w4i, 256, 331, KU4, (b - PB_W4) * 256 + tid);
    else if (b < PB_W6) wsplit_elem(fc5_w, g_w5i, 256, 256, KU2, (b - PB_W5) * 256 + tid);
    else if (b < PB_WO) wsplit_elem(fc6_w, g_w6i, 256, 256, KU2, (b - PB_W6) * 256 + tid);
    else if (b < PB_ET) wsplit_elem(out_w, g_woi, 267, 256, KU2, (b - PB_WO) * 256 + tid);
    else if (b < PB_ZC) {
        const int i = (b - PB_ET) * 256 + tid;
        const int code = i >> 5, j = i & 31;
        const float a = embed[(size_t)(2 * j) * KCODE + code];
        const float bb = embed[(size_t)(2 * j + 1) * KCODE + code];
        uint32_t l; uint32_t h = split_pack(a, bb, l);
        g_eth[i] = h; g_etl[i] = l;
        float s = a * a + bb * bb;
        #pragma unroll
        for (int off = 16; off; off >>= 1) s += __shfl_down_sync(0xffffffffu, s, off);
        if (j == 0) g_esq[code] = s;
    } else {
        const int i = (b - PB_ZC) * 256 + tid;
        if (i < KCODE) g_counts[i] = 0;
    }
}

__global__ void __launch_bounds__(256) finalize_kernel(float* __restrict__ out) {
    __shared__ float red[256];
    const int t = threadIdx.x;
    float s = 0.f;
    for (int i = t; i < 512; i += 256) s += g_partials[i];
    red[t] = s;
    for (int st = 128; st > 0; st >>= 1) { __syncthreads(); if (t < st) red[t] += red[t + st]; }
    __syncthreads();
    float loss = red[0] / (float)((size_t)BB * LDIM);
    __syncthreads();
    float e = 0.f;
    for (int k = t; k < KCODE; k += 256) {
        float p = (float)g_counts[k] / (float)BB;
        e += p * logf(p + 1e-10f);
    }
    red[t] = e;
    for (int st = 128; st > 0; st >>= 1) { __syncthreads(); if (t < st) red[t] += red[t + st]; }
    __syncthreads();
    if (t == 0) {
        out[(size_t)BB * FDIM] = loss;
        out[(size_t)BB * FDIM + 1] = expf(-red[0]);
    }
}

// ---------------- host launcher ----------------
extern "C" void kernel_launch(void* const* d_in, const int* in_sizes, int n_in,
                              void* d_out, int out_size)
{
    const float* x     = (const float*)d_in[0];
    const float* c     = (const float*)d_in[1];
    const float* fc1_w = (const float*)d_in[2];
    const float* fc1_b = (const float*)d_in[3];
    const float* fc2_w = (const float*)d_in[4];
    const float* fc2_b = (const float*)d_in[5];
    const float* fc3_w = (const float*)d_in[6];
    const float* fc3_b = (const float*)d_in[7];
    const float* mu_w  = (const float*)d_in[8];
    const float* mu_b  = (const float*)d_in[9];
    const float* fc4_w = (const float*)d_in[10];
    const float* fc4_b = (const float*)d_in[11];
    const float* fc5_w = (const float*)d_in[12];
    const float* fc5_b = (const float*)d_in[13];
    const float* fc6_w = (const float*)d_in[14];
    const float* fc6_b = (const float*)d_in[15];
    const float* out_w = (const float*)d_in[16];
    const float* out_b = (const float*)d_in[17];
    const float* embed = (const float*)d_in[18];
    float* out = (float*)d_out;

    const int NET_SMEM = 55296 * 4;   // 221184 B
    cudaFuncSetAttribute(fused_net, cudaFuncAttributeMaxDynamicSharedMemorySize, NET_SMEM);

    prep_all<<<PB_END, 256>>>(fc1_w, fc2_w, fc3_w, mu_w, fc4_w, fc5_w, fc6_w, out_w, embed);
    fused_net<<<BB / 128, 512, NET_SMEM>>>(x, c, fc1_b, fc2_b, fc3_b, mu_b,
                                           fc4_b, fc5_b, fc6_b, out_b, embed, out);
    finalize_kernel<<<1, 256>>>(out);
}

// round 16
// speedup vs baseline: 1.0663x; 1.0663x over previous
#include <cuda_runtime.h>
#include <cuda_fp16.h>
#include <cstdint>
#include <math.h>

#define BB 65536
#define FDIM 267
#define HDIM 256
#define LDIM 64
#define KCODE 1024

// pair strides (uint2 per 2 K-elems), K padded to 32-pair (64-elem) chunk multiples
#define KU1 288   // fc1: K=534 -> 9 chunks (fp32 path)
#define KU2 128   // K=256 -> 4 chunks
#define KU4 192   // fc4: K=331 -> 6 chunks (fp32 path)

// ---------------- scratch (device globals) ----------------
__device__ uint2 g_h1p[BB * KU2];
__device__ uint2 g_h2p[BB * KU2];
__device__ float g_q[BB * LDIM];
__device__ float g_esq[KCODE];
__device__ int   g_counts[KCODE];
__device__ float g_partials[512];
__device__ uint32_t g_eth[KCODE * 32], g_etl[KCODE * 32];  // codebook pairs [code][l/2]
__device__ uint2 g_w1i[256 * KU1];
__device__ uint2 g_w2i[256 * KU2];
__device__ uint2 g_w3i[256 * KU2];
__device__ uint2 g_wmi[128 * KU2];
__device__ uint2 g_w4i[256 * KU4];
__device__ uint2 g_w5i[256 * KU2];
__device__ uint2 g_w6i[256 * KU2];
__device__ uint2 g_woi[384 * KU2];

// ---------------- helpers ----------------
__device__ __forceinline__ float hi32(float a) {
    return __uint_as_float(__float_as_uint(a) & 0xFFFFE000u);
}
__device__ __forceinline__ uint32_t packh(float x, float y) {
    uint32_t d;
    asm("cvt.rn.f16x2.f32 %0, %1, %2;" : "=r"(d) : "f"(y), "f"(x));
    return d;
}
__device__ __forceinline__ uint32_t split_pack(float a, float b, uint32_t& lo) {
    float ha = hi32(a), hb = hi32(b);
    lo = packh(a - ha, b - hb);
    return packh(ha, hb);
}
__device__ __forceinline__ uint32_t smem_u32(const void* p) {
    uint32_t a;
    asm("{ .reg .u64 t; cvta.to.shared.u64 t, %1; cvt.u32.u64 %0, t; }" : "=r"(a) : "l"(p));
    return a;
}
__device__ __forceinline__ void ldm_x4(uint32_t* d, uint32_t a) {
    asm volatile("ldmatrix.sync.aligned.m8n8.x4.shared.b16 {%0,%1,%2,%3}, [%4];"
        : "=r"(d[0]), "=r"(d[1]), "=r"(d[2]), "=r"(d[3]) : "r"(a));
}
__device__ __forceinline__ void mma16(float* d, const uint32_t* a, const uint32_t* b) {
    asm volatile(
        "mma.sync.aligned.m16n8k16.row.col.f32.f16.f16.f32 "
        "{%0,%1,%2,%3},{%4,%5,%6,%7},{%8,%9},{%0,%1,%2,%3};"
        : "+f"(d[0]), "+f"(d[1]), "+f"(d[2]), "+f"(d[3])
        : "r"(a[0]), "r"(a[1]), "r"(a[2]), "r"(a[3]), "r"(b[0]), "r"(b[1]));
}
__device__ __forceinline__ void sts64(uint32_t* p, uint32_t x, uint32_t y) {
    *(uint2*)p = make_uint2(x, y);
}

// ---------------- fp16x3 HMMA GEMM, template on A-source (proven R12/R13/R14) ----------------
template <bool PAIRS_A>
__global__ void __launch_bounds__(512, 1) mma_gemm(
    const float* __restrict__ A0, int W0,
    const float* __restrict__ A1, int W1,
    const uint2* __restrict__ Ap, int KUa,
    const uint2* __restrict__ Wt, int KUb,
    const float* __restrict__ bias,
    float* __restrict__ Cf, uint2* __restrict__ Cp, int NUp,
    int N, int K, int relu)
{
    extern __shared__ uint32_t smu[];

    const int tid = threadIdx.x, lane = tid & 31, wid = tid >> 5;
    const int m0 = blockIdx.y * 128, bn = blockIdx.x * 128;
    const int wm0 = (wid >> 2) * 32, wn0 = (wid & 3) * 32;
    const int r = lane >> 2, kq = lane & 3;
    const int NC = (K + 63) >> 6;
    const int prow = tid >> 4;
    const int pj   = tid & 15;

    const uint32_t sbase = smem_u32(smu);
    const int g = lane >> 3, lr = lane & 7;
    uint32_t aA[2], aB[2];
    #pragma unroll
    for (int mt = 0; mt < 2; mt++) {
        const uint32_t row = wm0 + mt * 16 + (g & 1) * 8 + lr;
        aA[mt] = sbase + 4u * (row * 36 + (g >> 1) * 4);
    }
    #pragma unroll
    for (int np = 0; np < 2; np++) {
        const uint32_t n = wn0 + (2 * np + (g >> 1)) * 8 + lr;
        aB[np] = sbase + 4u * (9216 + n * 36 + (g & 1) * 4);
    }

    float acc[2][4][4];
    #pragma unroll
    for (int i = 0; i < 2; i++)
        #pragma unroll
        for (int j = 0; j < 4; j++)
            #pragma unroll
            for (int e = 0; e < 4; e++) acc[i][j][e] = 0.f;

    float4 a4[4];
    uint4  aU[4];
    uint4  b4[4];

    auto prefetch = [&](int c) {
        const size_t bo = (size_t)c * 32 + 2 * pj;
        #pragma unroll
        for (int p = 0; p < 4; p++) {
            const int row = p * 32 + prow;
            if (PAIRS_A) {
                aU[p] = *(const uint4*)&Ap[(size_t)(m0 + row) * KUa + bo];
            } else {
                const int kg0 = c * 64 + 4 * pj;
                float v[4];
                #pragma unroll
                for (int e = 0; e < 4; e++) {
                    const int kg = kg0 + e;
                    float t = 0.f;
                    if (kg < K)
                        t = (kg < W0) ? A0[(size_t)(m0 + row) * W0 + kg]
                                      : A1[(size_t)(m0 + row) * W1 + (kg - W0)];
                    v[e] = t;
                }
                a4[p] = make_float4(v[0], v[1], v[2], v[3]);
            }
            b4[p] = *(const uint4*)&Wt[(size_t)(bn + row) * KUb + bo];
        }
    };
    auto store = [&](int b) {
        uint32_t* base = smu + b * 18432;
        #pragma unroll
        for (int p = 0; p < 4; p++) {
            const int o = (p * 32 + prow) * 36 + 2 * pj;
            if (PAIRS_A) {
                sts64(base + o, aU[p].x, aU[p].z);
                sts64(base + 4608 + o, aU[p].y, aU[p].w);
            } else {
                const float h0 = hi32(a4[p].x), h1 = hi32(a4[p].y);
                const float h2 = hi32(a4[p].z), h3 = hi32(a4[p].w);
                sts64(base + o, packh(h0, h1), packh(h2, h3));
                sts64(base + 4608 + o,
                      packh(a4[p].x - h0, a4[p].y - h1),
                      packh(a4[p].z - h2, a4[p].w - h3));
            }
            sts64(base + 9216 + o, b4[p].x, b4[p].z);
            sts64(base + 13824 + o, b4[p].y, b4[p].w);
        }
    };
    auto compute = [&]() {
        #pragma unroll
        for (int ks = 0; ks < 4; ks++) {
            const uint32_t ko = ks * 32u;
            uint32_t ah[2][4], al[2][4], bh[4][2], bl[4][2];
            ldm_x4(ah[0], aA[0] + ko);
            ldm_x4(ah[1], aA[1] + ko);
            ldm_x4(al[0], aA[0] + ko + 18432u);
            ldm_x4(al[1], aA[1] + ko + 18432u);
            ldm_x4(&bh[0][0], aB[0] + ko);
            ldm_x4(&bh[2][0], aB[1] + ko);
            ldm_x4(&bl[0][0], aB[0] + ko + 18432u);
            ldm_x4(&bl[2][0], aB[1] + ko + 18432u);
            #pragma unroll
            for (int mt = 0; mt < 2; mt++)
                #pragma unroll
                for (int nt = 0; nt < 4; nt++) {
                    mma16(acc[mt][nt], ah[mt], bh[nt]);
                    mma16(acc[mt][nt], ah[mt], bl[nt]);
                    mma16(acc[mt][nt], al[mt], bh[nt]);
                }
        }
    };

    prefetch(0); store(0); __syncthreads();
    int32_t dshift = 73728;
    for (int c = 0; c < NC; c++) {
        if (c + 1 < NC) prefetch(c + 1);
        compute();
        if (c + 1 < NC) store((c + 1) & 1);
        __syncthreads();
        if (c + 1 < NC) {
            aA[0] += dshift; aA[1] += dshift;
            aB[0] += dshift; aB[1] += dshift;
            dshift = -dshift;
        }
    }

    const bool evenN = (N & 1) == 0;
    #pragma unroll
    for (int mt = 0; mt < 2; mt++) {
        #pragma unroll
        for (int q = 0; q < 2; q++) {
            const int row = m0 + wm0 + mt * 16 + q * 8 + r;
            #pragma unroll
            for (int nt = 0; nt < 4; nt++) {
                const int n = bn + wn0 + nt * 8 + 2 * kq;
                float v0 = acc[mt][nt][q * 2 + 0];
                float v1 = acc[mt][nt][q * 2 + 1];
                if (n + 1 < N) {
                    float o0 = v0 + bias[n];
                    float o1 = v1 + bias[n + 1];
                    if (relu) { o0 = fmaxf(o0, 0.f); o1 = fmaxf(o1, 0.f); }
                    if (Cp) {
                        uint32_t l; uint32_t h = split_pack(o0, o1, l);
                        Cp[(size_t)row * NUp + (n >> 1)] = make_uint2(h, l);
                    }
                    if (Cf) {
                        if (evenN) {
                            float2 p; p.x = o0; p.y = o1;
                            *(float2*)&Cf[(size_t)row * N + n] = p;
                        } else {
                            Cf[(size_t)row * N + n] = o0;
                            Cf[(size_t)row * N + n + 1] = o1;
                        }
                    }
                } else if (n < N && Cf) {
                    float o0 = v0 + bias[n];
                    if (relu) o0 = fmaxf(o0, 0.f);
                    Cf[(size_t)row * N + n] = o0;
                }
            }
        }
    }
}

// ---------------- fused VQ: mu-GEMM + argmin + gather + loss (proven R13/R14) ----------------
__global__ void __launch_bounds__(512, 1) vq_mma(const float* __restrict__ embed,
                                                 const float* __restrict__ mu_b)
{
    extern __shared__ uint32_t smv[];
    uint32_t* Mh = smv;
    uint32_t* Ml = smv + 4608;
    uint32_t* Eh = smv + 9216;
    uint32_t* El = smv + 13824;
    float* esq_s = (float*)(smv + 36864);

    __shared__ float sbest[16][2][2][8];
    __shared__ int   sidx[16][2][2][8];
    __shared__ int   rowidx[128];
    __shared__ float wsum[16];

    const int tid = threadIdx.x, lane = tid & 31, wid = tid >> 5;
    const int m0 = blockIdx.x * 128;
    const int wm0 = (wid >> 2) * 32;
    const int wq  = wid & 3;
    const int wn0 = wq * 32;
    const int r = lane >> 2, kq = lane & 3;
    const int prow = tid >> 4, pj = tid & 15;

    const uint32_t sbase = smem_u32(smv);
    const int g = lane >> 3, lr = lane & 7;

    #pragma unroll
    for (int i = tid; i < KCODE; i += 512) esq_s[i] = g_esq[i];

    // ===== phase 1: mu = h1p * Wm^T + mu_b =====
    {
        uint32_t p1A[2], p1B;
        #pragma unroll
        for (int mt = 0; mt < 2; mt++) {
            const uint32_t row = wm0 + mt * 16 + (g & 1) * 8 + lr;
            p1A[mt] = sbase + 36864u + 4u * (row * 36 + (g >> 1) * 4);
        }
        {
            const uint32_t n = wq * 16 + (g >> 1) * 8 + lr;
            p1B = sbase + 110592u + 4u * (n * 36 + (g & 1) * 4);
        }

        float acc1[2][2][4];
        #pragma unroll
        for (int i = 0; i < 2; i++)
            #pragma unroll
            for (int j = 0; j < 2; j++)
                #pragma unroll
                for (int e = 0; e < 4; e++) acc1[i][j][e] = 0.f;

        uint4 aU[4], bU[2];
        auto pf1 = [&](int c) {
            const size_t ao = (size_t)c * 32 + 2 * pj;
            #pragma unroll
            for (int p = 0; p < 4; p++)
                aU[p] = *(const uint4*)&g_h1p[(size_t)(m0 + p * 32 + prow) * KU2 + ao];
            #pragma unroll
            for (int p = 0; p < 2; p++)
                bU[p] = *(const uint4*)&g_wmi[(size_t)(p * 32 + prow) * KU2 + ao];
        };
        auto st1 = [&](int b) {
            uint32_t* A = smv + 9216 + b * 9216;
            uint32_t* Bq = smv + 27648 + b * 4608;
            #pragma unroll
            for (int p = 0; p < 4; p++) {
                const int o = (p * 32 + prow) * 36 + 2 * pj;
                sts64(A + o, aU[p].x, aU[p].z);
                sts64(A + 4608 + o, aU[p].y, aU[p].w);
            }
            #pragma unroll
            for (int p = 0; p < 2; p++) {
                const int o = (p * 32 + prow) * 36 + 2 * pj;
                sts64(Bq + o, bU[p].x, bU[p].z);
                sts64(Bq + 2304 + o, bU[p].y, bU[p].w);
            }
        };
        auto cmp1 = [&](int b) {
            const uint32_t abuf = (uint32_t)b * 36864u;
            const uint32_t bbuf = (uint32_t)b * 18432u;
            #pragma unroll
            for (int ks = 0; ks < 4; ks++) {
                const uint32_t ko = ks * 32u;
                uint32_t ah[2][4], al[2][4], bh[2][2], bl[2][2];
                ldm_x4(ah[0], p1A[0] + abuf + ko);
                ldm_x4(ah[1], p1A[1] + abuf + ko);
                ldm_x4(al[0], p1A[0] + abuf + ko + 18432u);
                ldm_x4(al[1], p1A[1] + abuf + ko + 18432u);
                ldm_x4(&bh[0][0], p1B + bbuf + ko);
                ldm_x4(&bl[0][0], p1B + bbuf + ko + 9216u);
                #pragma unroll
                for (int mt = 0; mt < 2; mt++)
                    #pragma unroll
                    for (int nt = 0; nt < 2; nt++) {
                        mma16(acc1[mt][nt], ah[mt], bh[nt]);
                        mma16(acc1[mt][nt], ah[mt], bl[nt]);
                        mma16(acc1[mt][nt], al[mt], bh[nt]);
                    }
            }
        };

        pf1(0); st1(0); __syncthreads();
        for (int c = 0; c < 4; c++) {
            if (c < 3) pf1(c + 1);
            cmp1(c & 1);
            if (c < 3) st1((c + 1) & 1);
            __syncthreads();
        }

        #pragma unroll
        for (int mt = 0; mt < 2; mt++)
            #pragma unroll
            for (int qq = 0; qq < 2; qq++) {
                const int m = wm0 + mt * 16 + qq * 8 + r;
                #pragma unroll
                for (int nt = 0; nt < 2; nt++) {
                    const int n = wq * 16 + nt * 8 + 2 * kq;
                    const float o0 = acc1[mt][nt][qq * 2 + 0] + mu_b[n];
                    const float o1 = acc1[mt][nt][qq * 2 + 1] + mu_b[n + 1];
                    uint32_t l; uint32_t h = split_pack(o0, o1, l);
                    Mh[m * 36 + (n >> 1)] = h;
                    Ml[m * 36 + (n >> 1)] = l;
                }
            }
    }

    // ===== phase 2: argmin =====
    float best[2][2];
    int   bidx[2][2];
    #pragma unroll
    for (int i = 0; i < 2; i++)
        #pragma unroll
        for (int j = 0; j < 2; j++) { best[i][j] = 3.4e38f; bidx[i][j] = 0; }

    uint32_t aM[2], aE[2];
    #pragma unroll
    for (int mt = 0; mt < 2; mt++) {
        const uint32_t row = wm0 + mt * 16 + (g & 1) * 8 + lr;
        aM[mt] = sbase + 4u * (row * 36 + (g >> 1) * 4);
    }
    #pragma unroll
    for (int np = 0; np < 2; np++) {
        const uint32_t n = wn0 + (2 * np + (g >> 1)) * 8 + lr;
        aE[np] = sbase + 4u * (9216 + n * 36 + (g & 1) * 4);
    }

    uint32_t uh[8], ul[8];
    for (int ct = 0; ct < 8; ct++) {
        #pragma unroll
        for (int ps = 0; ps < 8; ps++) {
            const int row = ps * 16 + wid;
            uh[ps] = g_eth[(size_t)(ct * 128 + row) * 32 + lane];
            ul[ps] = g_etl[(size_t)(ct * 128 + row) * 32 + lane];
        }
        __syncthreads();
        #pragma unroll
        for (int ps = 0; ps < 8; ps++) {
            const int row = ps * 16 + wid;
            Eh[row * 36 + lane] = uh[ps];
            El[row * 36 + lane] = ul[ps];
        }
        __syncthreads();

        float acc[2][4][4];
        #pragma unroll
        for (int i = 0; i < 2; i++)
            #pragma unroll
            for (int j = 0; j < 4; j++)
                #pragma unroll
                for (int e = 0; e < 4; e++) acc[i][j][e] = 0.f;

        #pragma unroll
        for (int ks = 0; ks < 4; ks++) {
            const uint32_t ko = ks * 32u;
            uint32_t ah[2][4], al[2][4], bh[4][2], bl[4][2];
            ldm_x4(ah[0], aM[0] + ko);
            ldm_x4(ah[1], aM[1] + ko);
            ldm_x4(al[0], aM[0] + ko + 18432u);
            ldm_x4(al[1], aM[1] + ko + 18432u);
            ldm_x4(&bh[0][0], aE[0] + ko);
            ldm_x4(&bh[2][0], aE[1] + ko);
            ldm_x4(&bl[0][0], aE[0] + ko + 18432u);
            ldm_x4(&bl[2][0], aE[1] + ko + 18432u);
            #pragma unroll
            for (int mt = 0; mt < 2; mt++)
                #pragma unroll
                for (int nt = 0; nt < 4; nt++) {
                    mma16(acc[mt][nt], ah[mt], bh[nt]);
                    mma16(acc[mt][nt], ah[mt], bl[nt]);
                    mma16(acc[mt][nt], al[mt], bh[nt]);
                }
        }

        #pragma unroll
        for (int mt = 0; mt < 2; mt++)
            #pragma unroll
            for (int q = 0; q < 2; q++)
                #pragma unroll
                for (int nt = 0; nt < 4; nt++)
                    #pragma unroll
                    for (int e = 0; e < 2; e++) {
                        const int code = ct * 128 + wn0 + nt * 8 + 2 * kq + e;
                        const float sc = esq_s[code] - 2.f * acc[mt][nt][q * 2 + e];
                        if (sc < best[mt][q]) { best[mt][q] = sc; bidx[mt][q] = code; }
                    }
        __syncthreads();
    }

    #pragma unroll
    for (int mt = 0; mt < 2; mt++)
        #pragma unroll
        for (int q = 0; q < 2; q++) {
            float b = best[mt][q]; int ix = bidx[mt][q];
            #pragma unroll
            for (int s = 1; s <= 2; s <<= 1) {
                const float ob = __shfl_xor_sync(0xffffffffu, b, s);
                const int   oi = __shfl_xor_sync(0xffffffffu, ix, s);
                if (ob < b || (ob == b && oi < ix)) { b = ob; ix = oi; }
            }
            if (kq == 0) { sbest[wid][mt][q][r] = b; sidx[wid][mt][q][r] = ix; }
        }
    __syncthreads();

    if (wq == 0 && kq == 0) {
        #pragma unroll
        for (int mt = 0; mt < 2; mt++)
            #pragma unroll
            for (int q = 0; q < 2; q++) {
                float b0 = sbest[wid][mt][q][r]; int i0 = sidx[wid][mt][q][r];
                #pragma unroll
                for (int w2 = 1; w2 < 4; w2++) {
                    float b1 = sbest[wid + w2][mt][q][r]; int i1 = sidx[wid + w2][mt][q][r];
                    if (b1 < b0 || (b1 == b0 && i1 < i0)) { b0 = b1; i0 = i1; }
                }
                rowidx[wm0 + mt * 16 + r + q * 8] = i0;
            }
    }
    __syncthreads();

    // ===== phase 3: gather q + loss + histogram =====
    {
        float lsum = 0.f;
        #pragma unroll
        for (int rr = 0; rr < 8; rr++) {
            const int row = wid * 8 + rr;
            const int idx = rowidx[row];
            const float e0 = embed[(size_t)(2 * lane) * KCODE + idx];
            const float e1 = embed[(size_t)(2 * lane + 1) * KCODE + idx];
            float2 qv; qv.x = e0; qv.y = e1;
            *(float2*)&g_q[(size_t)(m0 + row) * LDIM + 2 * lane] = qv;
            const __half2 H = *(const __half2*)&Mh[row * 36 + lane];
            const __half2 L = *(const __half2*)&Ml[row * 36 + lane];
            const float mu0 = __half2float(H.x) + __half2float(L.x);
            const float mu1 = __half2float(H.y) + __half2float(L.y);
            const float d0 = e0 - mu0, d1 = e1 - mu1;
            lsum += d0 * d0 + d1 * d1;
            if (lane == 0) atomicAdd(&g_counts[idx], 1);
        }
        #pragma unroll
        for (int off = 16; off; off >>= 1) lsum += __shfl_down_sync(0xffffffffu, lsum, off);
        if (lane == 0) wsum[wid] = lsum;
        __syncthreads();
        if (tid == 0) {
            float t = 0.f;
            #pragma unroll
            for (int i = 0; i < 16; i++) t += wsum[i];
            g_partials[blockIdx.x] = t;
        }
    }
}

// ---------------- single fused prep kernel (proven R14) ----------------
__device__ __forceinline__ void wsplit_elem(const float* __restrict__ W, uint2* __restrict__ out,
                                            int N, int K, int KU, int i)
{
    int n = i / KU, j = i - n * KU;
    int k0 = 2 * j;
    float a = (n < N && k0 < K) ? W[(size_t)n * K + k0] : 0.f;
    float b = (n < N && k0 + 1 < K) ? W[(size_t)n * K + k0 + 1] : 0.f;
    uint32_t l; uint32_t h = split_pack(a, b, l);
    out[i] = make_uint2(h, l);
}

#define PB_W1 0
#define PB_W2 (PB_W1 + (256 * KU1) / 256)
#define PB_W3 (PB_W2 + (256 * KU2) / 256)
#define PB_WM (PB_W3 + (256 * KU2) / 256)
#define PB_W4 (PB_WM + (128 * KU2) / 256)
#define PB_W5 (PB_W4 + (256 * KU4) / 256)
#define PB_W6 (PB_W5 + (256 * KU2) / 256)
#define PB_WO (PB_W6 + (256 * KU2) / 256)
#define PB_ET (PB_WO + (384 * KU2) / 256)
#define PB_ZC (PB_ET + (KCODE * 32) / 256)
#define PB_END (PB_ZC + 4)

__global__ void __launch_bounds__(256) prep_all(
    const float* __restrict__ fc1_w, const float* __restrict__ fc2_w,
    const float* __restrict__ fc3_w, const float* __restrict__ mu_w,
    const float* __restrict__ fc4_w, const float* __restrict__ fc5_w,
    const float* __restrict__ fc6_w, const float* __restrict__ out_w,
    const float* __restrict__ embed)
{
    const int b = blockIdx.x, tid = threadIdx.x;
    if (b < PB_W2)      wsplit_elem(fc1_w, g_w1i, 256, 534, KU1, (b - PB_W1) * 256 + tid);
    else if (b < PB_W3) wsplit_elem(fc2_w, g_w2i, 256, 256, KU2, (b - PB_W2) * 256 + tid);
    else if (b < PB_WM) wsplit_elem(fc3_w, g_w3i, 256, 256, KU2, (b - PB_W3) * 256 + tid);
    else if (b < PB_W4) wsplit_elem(mu_w,  g_wmi, 64,  256, KU2, (b - PB_WM) * 256 + tid);
    else if (b < PB_W5) wsplit_elem(fc4_w, g_w4i, 256, 331, KU4, (b - PB_W4) * 256 + tid);
    else if (b < PB_W6) wsplit_elem(fc5_w, g_w5i, 256, 256, KU2, (b - PB_W5) * 256 + tid);
    else if (b < PB_WO) wsplit_elem(fc6_w, g_w6i, 256, 256, KU2, (b - PB_W6) * 256 + tid);
    else if (b < PB_ET) wsplit_elem(out_w, g_woi, 267, 256, KU2, (b - PB_WO) * 256 + tid);
    else if (b < PB_ZC) {
        const int i = (b - PB_ET) * 256 + tid;
        const int code = i >> 5, j = i & 31;
        const float a = embed[(size_t)(2 * j) * KCODE + code];
        const float bb = embed[(size_t)(2 * j + 1) * KCODE + code];
        uint32_t l; uint32_t h = split_pack(a, bb, l);
        g_eth[i] = h; g_etl[i] = l;
        float s = a * a + bb * bb;
        #pragma unroll
        for (int off = 16; off; off >>= 1) s += __shfl_down_sync(0xffffffffu, s, off);
        if (j == 0) g_esq[code] = s;
    } else {
        const int i = (b - PB_ZC) * 256 + tid;
        if (i < KCODE) g_counts[i] = 0;
    }
}

__global__ void __launch_bounds__(256) finalize_kernel(float* __restrict__ out) {
    __shared__ float red[256];
    const int t = threadIdx.x;
    float s = 0.f;
    for (int i = t; i < 512; i += 256) s += g_partials[i];
    red[t] = s;
    for (int st = 128; st > 0; st >>= 1) { __syncthreads(); if (t < st) red[t] += red[t + st]; }
    __syncthreads();
    float loss = red[0] / (float)((size_t)BB * LDIM);
    __syncthreads();
    float e = 0.f;
    for (int k = t; k < KCODE; k += 256) {
        float p = (float)g_counts[k] / (float)BB;
        e += p * logf(p + 1e-10f);
    }
    red[t] = e;
    for (int st = 128; st > 0; st >>= 1) { __syncthreads(); if (t < st) red[t] += red[t + st]; }
    __syncthreads();
    if (t == 0) {
        out[(size_t)BB * FDIM] = loss;
        out[(size_t)BB * FDIM + 1] = expf(-red[0]);
    }
}

// ---------------- host launcher ----------------
#define SYM(v, s) cudaGetSymbolAddress((void**)&v, s)

extern "C" void kernel_launch(void* const* d_in, const int* in_sizes, int n_in,
                              void* d_out, int out_size)
{
    const float* x     = (const float*)d_in[0];
    const float* c     = (const float*)d_in[1];
    const float* fc1_w = (const float*)d_in[2];
    const float* fc1_b = (const float*)d_in[3];
    const float* fc2_w = (const float*)d_in[4];
    const float* fc2_b = (const float*)d_in[5];
    const float* fc3_w = (const float*)d_in[6];
    const float* fc3_b = (const float*)d_in[7];
    const float* mu_w  = (const float*)d_in[8];
    const float* mu_b  = (const float*)d_in[9];
    const float* fc4_w = (const float*)d_in[10];
    const float* fc4_b = (const float*)d_in[11];
    const float* fc5_w = (const float*)d_in[12];
    const float* fc5_b = (const float*)d_in[13];
    const float* fc6_w = (const float*)d_in[14];
    const float* fc6_b = (const float*)d_in[15];
    const float* out_w = (const float*)d_in[16];
    const float* out_b = (const float*)d_in[17];
    const float* embed = (const float*)d_in[18];
    float* out = (float*)d_out;

    float *q;
    uint2 *h1p, *h2p;
    uint2 *w1i, *w2i, *w3i, *wmi, *w4i, *w5i, *w6i, *woi;
    SYM(q, g_q);
    SYM(h1p, g_h1p); SYM(h2p, g_h2p);
    SYM(w1i, g_w1i); SYM(w2i, g_w2i); SYM(w3i, g_w3i); SYM(wmi, g_wmi);
    SYM(w4i, g_w4i); SYM(w5i, g_w5i); SYM(w6i, g_w6i); SYM(woi, g_woi);

    const int GEMM_SMEM = 2 * 18432 * 4;            // 147456 B
    const int VQ_SMEM   = 37888 * 4;                // 151552 B
    cudaFuncSetAttribute(mma_gemm<false>, cudaFuncAttributeMaxDynamicSharedMemorySize, GEMM_SMEM);
    cudaFuncSetAttribute(mma_gemm<true>,  cudaFuncAttributeMaxDynamicSharedMemorySize, GEMM_SMEM);
    cudaFuncSetAttribute(vq_mma, cudaFuncAttributeMaxDynamicSharedMemorySize, VQ_SMEM);

    const dim3 blk(512);
    const dim3 g256(2, BB / 128);
    const dim3 g267(3, BB / 128);

    // single fused prep launch
    prep_all<<<PB_END, 256>>>(fc1_w, fc2_w, fc3_w, mu_w, fc4_w, fc5_w, fc6_w, out_w, embed);

    // encoder
    mma_gemm<false><<<g256, blk, GEMM_SMEM>>>(x, FDIM, c, FDIM, nullptr, 0, w1i, KU1, fc1_b,
                                              nullptr, h1p, KU2, HDIM, 534, 1);
    mma_gemm<true><<<g256, blk, GEMM_SMEM>>>(nullptr, 0, nullptr, 0, h1p, KU2, w2i, KU2, fc2_b,
                                             nullptr, h2p, KU2, HDIM, HDIM, 1);
    mma_gemm<true><<<g256, blk, GEMM_SMEM>>>(nullptr, 0, nullptr, 0, h2p, KU2, w3i, KU2, fc3_b,
                                             nullptr, h1p, KU2, HDIM, HDIM, 1);

    // fused VQ: mu-GEMM + argmin + gather + loss
    vq_mma<<<BB / 128, 512, VQ_SMEM>>>(embed, mu_b);

    // decoder
    mma_gemm<false><<<g256, blk, GEMM_SMEM>>>(q, LDIM, c, FDIM, nullptr, 0, w4i, KU4, fc4_b,
                                              nullptr, h2p, KU2, HDIM, 331, 1);
    mma_gemm<true><<<g256, blk, GEMM_SMEM>>>(nullptr, 0, nullptr, 0, h2p, KU2, w5i, KU2, fc5_b,
                                             nullptr, h1p, KU2, HDIM, HDIM, 1);
    mma_gemm<true><<<g256, blk, GEMM_SMEM>>>(nullptr, 0, nullptr, 0, h1p, KU2, w6i, KU2, fc6_b,
                                             nullptr, h2p, KU2, HDIM, HDIM, 1);
    mma_gemm<true><<<g267, blk, GEMM_SMEM>>>(nullptr, 0, nullptr, 0, h2p, KU2, woi, KU2, out_b,
                                             out, nullptr, 0, FDIM, HDIM, 0);

    // scalars
    finalize_kernel<<<1, 256>>>(out);
}